// round 1
// baseline (speedup 1.0000x reference)
#include <cuda_runtime.h>
#include <math.h>

#define BATCH 64
#define CCH   512   // channels C
#define NPIX  1024  // H*W
#define DD    64    // D = C/8

// ---------------- scratch (static device arrays; no allocation) -------------
__device__ __align__(128) float g_q [BATCH * CCH * DD];          //  8.4 MB
__device__ __align__(128) float g_k [BATCH * CCH * DD];          //  8.4 MB
__device__ __align__(128) float g_at[(size_t)BATCH * CCH * CCH]; // 67 MB  At[b][j][i]
__device__ __align__(128) float g_m [(size_t)BATCH * CCH * CCH]; // 67 MB  M[b][j][c]
__device__ __align__(128) float g_ab[BATCH * CCH];               // At @ bias

// ============================================================================
// K1: q[b] = xf[b] @ Qm ; k[b] = xf[b] @ Km   (x tile loaded once for both)
// GEMM M=512 (c), N=64 (d, full), K=1024 (n). BM=64, BN=64, BK=16, 256 thr, 4x4.
// grid (CCH/64, BATCH)
// ============================================================================
__global__ __launch_bounds__(256) void qk_kernel(
    const float* __restrict__ x, const float* __restrict__ qm,
    const float* __restrict__ km)
{
    __shared__ float As[16][64];
    __shared__ float Qs[16][64];
    __shared__ float Ks[16][64];

    const int b    = blockIdx.y;
    const int row0 = blockIdx.x * 64;
    const float* A = x + (size_t)b * CCH * NPIX;

    const int tid = threadIdx.x;
    const int ty = tid / 16, tx = tid % 16;
    const int ar = tid / 4,  ac = (tid % 4) * 4;   // A: row=ar, k-offset ac..ac+3
    const int bk = tid / 16, bc = (tid % 16) * 4;  // B: k-row=bk, col bc..bc+3

    float cq[4][4] = {}, ck[4][4] = {};

    for (int k0 = 0; k0 < NPIX; k0 += 16) {
        float4 av = *(const float4*)&A[(size_t)(row0 + ar) * NPIX + k0 + ac];
        As[ac + 0][ar] = av.x; As[ac + 1][ar] = av.y;
        As[ac + 2][ar] = av.z; As[ac + 3][ar] = av.w;
        *(float4*)&Qs[bk][bc] = *(const float4*)&qm[(k0 + bk) * DD + bc];
        *(float4*)&Ks[bk][bc] = *(const float4*)&km[(k0 + bk) * DD + bc];
        __syncthreads();
#pragma unroll
        for (int kk = 0; kk < 16; kk++) {
            float a[4], bq[4], bb[4];
#pragma unroll
            for (int u = 0; u < 4; u++) a[u] = As[kk][ty * 4 + u];
#pragma unroll
            for (int v = 0; v < 4; v++) { bq[v] = Qs[kk][tx * 4 + v]; bb[v] = Ks[kk][tx * 4 + v]; }
#pragma unroll
            for (int u = 0; u < 4; u++)
#pragma unroll
                for (int v = 0; v < 4; v++) {
                    cq[u][v] = fmaf(a[u], bq[v], cq[u][v]);
                    ck[u][v] = fmaf(a[u], bb[v], ck[u][v]);
                }
        }
        __syncthreads();
    }
    float* qo = g_q + ((size_t)b * CCH + row0) * DD;
    float* ko = g_k + ((size_t)b * CCH + row0) * DD;
#pragma unroll
    for (int u = 0; u < 4; u++) {
        int r = (ty * 4 + u) * DD + tx * 4;
        *(float4*)&qo[r] = make_float4(cq[u][0], cq[u][1], cq[u][2], cq[u][3]);
        *(float4*)&ko[r] = make_float4(ck[u][0], ck[u][1], ck[u][2], ck[u][3]);
    }
}

// ============================================================================
// K2a: T[b][j][i] = exp(sigmoid( (q @ k^T)[i][j] ))   (transposed store)
// NT GEMM: M=512(i), N=512(j), K=64. BM=BN=64, BK=16, 256 thr, 4x4.
// grid (8 jtiles, 8 itiles, BATCH)
// ============================================================================
__global__ __launch_bounds__(256) void energy_kernel()
{
    __shared__ float Qs[16][64];   // [kk][i]
    __shared__ float Ks[16][64];   // [kk][j]
    __shared__ float Cs[64][68];   // [j][i] staging (68: f4-aligned, de-conflicted)

    const int b  = blockIdx.z;
    const int j0 = blockIdx.x * 64;
    const int i0 = blockIdx.y * 64;
    const float* Aq = g_q + ((size_t)b * CCH + i0) * DD;
    const float* Ak = g_k + ((size_t)b * CCH + j0) * DD;

    const int tid = threadIdx.x;
    const int ty = tid / 16, tx = tid % 16;
    const int ar = tid / 4,  ac = (tid % 4) * 4;

    float e[4][4] = {};

    for (int k0 = 0; k0 < DD; k0 += 16) {
        float4 av = *(const float4*)&Aq[ar * DD + k0 + ac];
        Qs[ac + 0][ar] = av.x; Qs[ac + 1][ar] = av.y;
        Qs[ac + 2][ar] = av.z; Qs[ac + 3][ar] = av.w;
        float4 bv = *(const float4*)&Ak[ar * DD + k0 + ac];
        Ks[ac + 0][ar] = bv.x; Ks[ac + 1][ar] = bv.y;
        Ks[ac + 2][ar] = bv.z; Ks[ac + 3][ar] = bv.w;
        __syncthreads();
#pragma unroll
        for (int kk = 0; kk < 16; kk++) {
            float a[4], bb[4];
#pragma unroll
            for (int u = 0; u < 4; u++) a[u]  = Qs[kk][ty * 4 + u];
#pragma unroll
            for (int v = 0; v < 4; v++) bb[v] = Ks[kk][tx * 4 + v];
#pragma unroll
            for (int u = 0; u < 4; u++)
#pragma unroll
                for (int v = 0; v < 4; v++) e[u][v] = fmaf(a[u], bb[v], e[u][v]);
        }
        __syncthreads();
    }
    // sigmoid -> exp, stage transposed
#pragma unroll
    for (int u = 0; u < 4; u++)
#pragma unroll
        for (int v = 0; v < 4; v++) {
            float s = 1.0f / (1.0f + expf(-e[u][v]));
            Cs[tx * 4 + v][ty * 4 + u] = expf(s);
        }
    __syncthreads();
    // coalesced write of the 64x64 transposed tile
    float* orow = g_at + ((size_t)b * CCH) * CCH;
    const int jj = tid / 4;
    const int st = (tid % 4) * 16;
    float* dst = &orow[(size_t)(j0 + jj) * CCH + i0 + st];
#pragma unroll
    for (int w = 0; w < 4; w++)
        *(float4*)&dst[w * 4] = *(float4*)&Cs[jj][st + w * 4];
}

// ============================================================================
// K2b: per (b,j): At[j][i] /= sum_i At[j][i];  g_ab[b][j] = sum_i At[j][i]*bias[i]
// grid BATCH*CCH, 128 threads
// ============================================================================
__global__ __launch_bounds__(128) void norm_kernel(const float* __restrict__ vb)
{
    __shared__ float sred[2][4];
    const int b = blockIdx.x >> 9;
    const int j = blockIdx.x & 511;
    float* row = g_at + ((size_t)(b << 9) + j) * CCH;

    const int i4 = threadIdx.x * 4;   // 128 thr * 4 = 512
    float4 v = *(const float4*)&row[i4];
    float4 w = *(const float4*)&vb[i4];
    float s  = v.x + v.y + v.z + v.w;
    float s2 = v.x * w.x + v.y * w.y + v.z * w.z + v.w * w.w;
#pragma unroll
    for (int o = 16; o > 0; o >>= 1) {
        s  += __shfl_xor_sync(0xffffffffu, s,  o);
        s2 += __shfl_xor_sync(0xffffffffu, s2, o);
    }
    const int wi = threadIdx.x >> 5, li = threadIdx.x & 31;
    if (li == 0) { sred[0][wi] = s; sred[1][wi] = s2; }
    __syncthreads();
    float tot  = sred[0][0] + sred[0][1] + sred[0][2] + sred[0][3];
    float tot2 = sred[1][0] + sred[1][1] + sred[1][2] + sred[1][3];
    float inv = 1.0f / tot;
    v.x *= inv; v.y *= inv; v.z *= inv; v.w *= inv;
    *(float4*)&row[i4] = v;
    if (threadIdx.x == 0) g_ab[(b << 9) + j] = tot2 * inv;
}

// ============================================================================
// SGEMM 128x128x8, 256 threads, 8x8/thread (4+4 split)  — used by K3 and K4
// ============================================================================
__global__ __launch_bounds__(256) void m_kernel(const float* __restrict__ W)
{
    __shared__ float As[8][128];
    __shared__ float Bs[8][128];
    const int b    = blockIdx.z;
    const int row0 = blockIdx.y * 128, col0 = blockIdx.x * 128;
    const float* A = g_at + (size_t)b * CCH * CCH;   // lda = 512
    float*       Co = g_m + (size_t)b * CCH * CCH;   // ldc = 512

    const int tid = threadIdx.x;
    const int ar = tid >> 1, ac = (tid & 1) * 4;
    const int bk = tid >> 5, bc = (tid & 31) * 4;
    const int tx = tid % 16, ty = tid / 16;

    float acc[8][8] = {};
    for (int k0 = 0; k0 < CCH; k0 += 8) {
        float4 av = *(const float4*)&A[(size_t)(row0 + ar) * CCH + k0 + ac];
        As[ac + 0][ar] = av.x; As[ac + 1][ar] = av.y;
        As[ac + 2][ar] = av.z; As[ac + 3][ar] = av.w;
        *(float4*)&Bs[bk][bc] = *(const float4*)&W[(size_t)(k0 + bk) * CCH + col0 + bc];
        __syncthreads();
#pragma unroll
        for (int kk = 0; kk < 8; kk++) {
            float a[8], bb[8];
            *(float4*)&a[0]  = *(float4*)&As[kk][ty * 4];
            *(float4*)&a[4]  = *(float4*)&As[kk][64 + ty * 4];
            *(float4*)&bb[0] = *(float4*)&Bs[kk][tx * 4];
            *(float4*)&bb[4] = *(float4*)&Bs[kk][64 + tx * 4];
#pragma unroll
            for (int u = 0; u < 8; u++)
#pragma unroll
                for (int v = 0; v < 8; v++) acc[u][v] = fmaf(a[u], bb[v], acc[u][v]);
        }
        __syncthreads();
    }
#pragma unroll
    for (int u = 0; u < 8; u++) {
        int r = row0 + ((u < 4) ? (ty * 4 + u) : (64 + ty * 4 + u - 4));
        *(float4*)&Co[(size_t)r * CCH + col0 + tx * 4]      = make_float4(acc[u][0], acc[u][1], acc[u][2], acc[u][3]);
        *(float4*)&Co[(size_t)r * CCH + col0 + 64 + tx * 4] = make_float4(acc[u][4], acc[u][5], acc[u][6], acc[u][7]);
    }
}

__global__ __launch_bounds__(256) void out_kernel(
    const float* __restrict__ x, float* __restrict__ out)
{
    __shared__ float As[8][128];
    __shared__ float Bs[8][128];
    const int b    = blockIdx.z;
    const int row0 = blockIdx.y * 128, col0 = blockIdx.x * 128;
    const float* A = g_m + (size_t)b * CCH * CCH;        // lda = 512
    const float* B = x  + (size_t)b * CCH * NPIX;        // ldb = 1024
    float*       Co = out + (size_t)b * CCH * NPIX;      // ldc = 1024

    const int tid = threadIdx.x;
    const int ar = tid >> 1, ac = (tid & 1) * 4;
    const int bk = tid >> 5, bc = (tid & 31) * 4;
    const int tx = tid % 16, ty = tid / 16;

    float acc[8][8] = {};
    for (int k0 = 0; k0 < CCH; k0 += 8) {
        float4 av = *(const float4*)&A[(size_t)(row0 + ar) * CCH + k0 + ac];
        As[ac + 0][ar] = av.x; As[ac + 1][ar] = av.y;
        As[ac + 2][ar] = av.z; As[ac + 3][ar] = av.w;
        *(float4*)&Bs[bk][bc] = *(const float4*)&B[(size_t)(k0 + bk) * NPIX + col0 + bc];
        __syncthreads();
#pragma unroll
        for (int kk = 0; kk < 8; kk++) {
            float a[8], bb[8];
            *(float4*)&a[0]  = *(float4*)&As[kk][ty * 4];
            *(float4*)&a[4]  = *(float4*)&As[kk][64 + ty * 4];
            *(float4*)&bb[0] = *(float4*)&Bs[kk][tx * 4];
            *(float4*)&bb[4] = *(float4*)&Bs[kk][64 + tx * 4];
#pragma unroll
            for (int u = 0; u < 8; u++)
#pragma unroll
                for (int v = 0; v < 8; v++) acc[u][v] = fmaf(a[u], bb[v], acc[u][v]);
        }
        __syncthreads();
    }
#pragma unroll
    for (int u = 0; u < 8; u++) {
        int r = row0 + ((u < 4) ? (ty * 4 + u) : (64 + ty * 4 + u - 4));
        float ab = g_ab[(b << 9) + r];
        *(float4*)&Co[(size_t)r * NPIX + col0 + tx * 4] =
            make_float4(acc[u][0] + ab, acc[u][1] + ab, acc[u][2] + ab, acc[u][3] + ab);
        *(float4*)&Co[(size_t)r * NPIX + col0 + 64 + tx * 4] =
            make_float4(acc[u][4] + ab, acc[u][5] + ab, acc[u][6] + ab, acc[u][7] + ab);
    }
}

// ============================================================================
extern "C" void kernel_launch(void* const* d_in, const int* in_sizes, int n_in,
                              void* d_out, int out_size)
{
    const float* x  = (const float*)d_in[0];   // [64,512,32,32]
    const float* qm = (const float*)d_in[1];   // [1024,64]
    const float* km = (const float*)d_in[2];   // [1024,64]
    const float* vw = (const float*)d_in[3];   // [512,512]
    const float* vb = (const float*)d_in[4];   // [512]
    float* out = (float*)d_out;

    qk_kernel    <<<dim3(CCH / 64, BATCH),        256>>>(x, qm, km);
    energy_kernel<<<dim3(CCH / 64, CCH / 64, BATCH), 256>>>();
    norm_kernel  <<<dim3(BATCH * CCH),            128>>>(vb);
    m_kernel     <<<dim3(CCH / 128, CCH / 128, BATCH), 256>>>(vw);
    out_kernel   <<<dim3(NPIX / 128, CCH / 128, BATCH), 256>>>(x, out);
}

// round 3
// speedup vs baseline: 2.0964x; 2.0964x over previous
#include <cuda_runtime.h>
#include <cstdint>
#include <math.h>

#define BATCH 64
#define CCH   512
#define NPIX  1024
#define DD    64

// ---------------- scratch (static device arrays; no allocation) -------------
__device__ __align__(128) float g_q [BATCH * CCH * DD];
__device__ __align__(128) float g_k [BATCH * CCH * DD];
__device__ __align__(128) float g_at[(size_t)BATCH * CCH * CCH]; // At[b][j][i], tf32-rounded
__device__ __align__(128) float g_m [(size_t)BATCH * CCH * CCH]; // M[b][j][c],  tf32-rounded
__device__ __align__(128) float g_ab[BATCH * CCH];
__device__ __align__(128) float g_wt[CCH * CCH];                 // W^T, tf32-rounded
__device__ __align__(128) float g_xt[(size_t)BATCH * NPIX * CCH];// x^T, tf32-rounded

// ---------------- helpers ----------------
__device__ __forceinline__ float to_tf32(float x) {
    uint32_t u;
    asm("cvt.rna.tf32.f32 %0, %1;" : "=r"(u) : "f"(x));
    return __uint_as_float(u);
}
__device__ __forceinline__ uint32_t smem_u32(const void* p) {
    uint32_t a;
    asm("{ .reg .u64 t; cvta.to.shared.u64 t, %1; cvt.u32.u64 %0, t; }" : "=r"(a) : "l"(p));
    return a;
}
__device__ __forceinline__ void cpa16(uint32_t d, const void* g) {
    asm volatile("cp.async.cg.shared.global [%0], [%1], 16;" :: "r"(d), "l"(g) : "memory");
}
__device__ __forceinline__ void cpa_commit() {
    asm volatile("cp.async.commit_group;" ::: "memory");
}
__device__ __forceinline__ void mma_tf32(float* c, const uint32_t* a, const uint32_t* b) {
    asm volatile(
        "mma.sync.aligned.m16n8k8.row.col.f32.tf32.tf32.f32 "
        "{%0,%1,%2,%3}, {%4,%5,%6,%7}, {%8,%9}, {%0,%1,%2,%3};"
        : "+f"(c[0]), "+f"(c[1]), "+f"(c[2]), "+f"(c[3])
        : "r"(a[0]), "r"(a[1]), "r"(a[2]), "r"(a[3]), "r"(b[0]), "r"(b[1]));
}

// ============================================================================
// K1: q,k = x @ {Qm,Km}
// ============================================================================
__global__ __launch_bounds__(256) void qk_kernel(
    const float* __restrict__ x, const float* __restrict__ qm,
    const float* __restrict__ km)
{
    __shared__ float As[16][64];
    __shared__ float Qs[16][64];
    __shared__ float Ks[16][64];

    const int b = blockIdx.y;
    const int row0 = blockIdx.x * 64;
    const float* A = x + (size_t)b * CCH * NPIX;

    const int tid = threadIdx.x;
    const int ty = tid / 16, tx = tid % 16;
    const int ar = tid / 4,  ac = (tid % 4) * 4;
    const int bk = tid / 16, bc = (tid % 16) * 4;

    float cq[4][4] = {}, ck[4][4] = {};
    for (int k0 = 0; k0 < NPIX; k0 += 16) {
        float4 av = *(const float4*)&A[(size_t)(row0 + ar) * NPIX + k0 + ac];
        As[ac + 0][ar] = av.x; As[ac + 1][ar] = av.y;
        As[ac + 2][ar] = av.z; As[ac + 3][ar] = av.w;
        *(float4*)&Qs[bk][bc] = *(const float4*)&qm[(k0 + bk) * DD + bc];
        *(float4*)&Ks[bk][bc] = *(const float4*)&km[(k0 + bk) * DD + bc];
        __syncthreads();
#pragma unroll
        for (int kk = 0; kk < 16; kk++) {
            float a[4], bq[4], bb[4];
#pragma unroll
            for (int u = 0; u < 4; u++) a[u] = As[kk][ty * 4 + u];
#pragma unroll
            for (int v = 0; v < 4; v++) { bq[v] = Qs[kk][tx * 4 + v]; bb[v] = Ks[kk][tx * 4 + v]; }
#pragma unroll
            for (int u = 0; u < 4; u++)
#pragma unroll
                for (int v = 0; v < 4; v++) {
                    cq[u][v] = fmaf(a[u], bq[v], cq[u][v]);
                    ck[u][v] = fmaf(a[u], bb[v], ck[u][v]);
                }
        }
        __syncthreads();
    }
    float* qo = g_q + ((size_t)b * CCH + row0) * DD;
    float* ko = g_k + ((size_t)b * CCH + row0) * DD;
#pragma unroll
    for (int u = 0; u < 4; u++) {
        int r = (ty * 4 + u) * DD + tx * 4;
        *(float4*)&qo[r] = make_float4(cq[u][0], cq[u][1], cq[u][2], cq[u][3]);
        *(float4*)&ko[r] = make_float4(ck[u][0], ck[u][1], ck[u][2], ck[u][3]);
    }
}

// ============================================================================
// K2a: At[b][j][i] = exp(sigmoid(q@k^T)) transposed store
// ============================================================================
__global__ __launch_bounds__(256) void energy_kernel()
{
    __shared__ float Qs[16][64];
    __shared__ float Ks[16][64];
    __shared__ float Cs[64][68];

    const int b  = blockIdx.z;
    const int j0 = blockIdx.x * 64;
    const int i0 = blockIdx.y * 64;
    const float* Aq = g_q + ((size_t)b * CCH + i0) * DD;
    const float* Ak = g_k + ((size_t)b * CCH + j0) * DD;

    const int tid = threadIdx.x;
    const int ty = tid / 16, tx = tid % 16;
    const int ar = tid / 4,  ac = (tid % 4) * 4;

    float e[4][4] = {};
    for (int k0 = 0; k0 < DD; k0 += 16) {
        float4 av = *(const float4*)&Aq[ar * DD + k0 + ac];
        Qs[ac + 0][ar] = av.x; Qs[ac + 1][ar] = av.y;
        Qs[ac + 2][ar] = av.z; Qs[ac + 3][ar] = av.w;
        float4 bv = *(const float4*)&Ak[ar * DD + k0 + ac];
        Ks[ac + 0][ar] = bv.x; Ks[ac + 1][ar] = bv.y;
        Ks[ac + 2][ar] = bv.z; Ks[ac + 3][ar] = bv.w;
        __syncthreads();
#pragma unroll
        for (int kk = 0; kk < 16; kk++) {
            float a[4], bb[4];
#pragma unroll
            for (int u = 0; u < 4; u++) a[u]  = Qs[kk][ty * 4 + u];
#pragma unroll
            for (int v = 0; v < 4; v++) bb[v] = Ks[kk][tx * 4 + v];
#pragma unroll
            for (int u = 0; u < 4; u++)
#pragma unroll
                for (int v = 0; v < 4; v++) e[u][v] = fmaf(a[u], bb[v], e[u][v]);
        }
        __syncthreads();
    }
#pragma unroll
    for (int u = 0; u < 4; u++)
#pragma unroll
        for (int v = 0; v < 4; v++) {
            float s = 1.0f / (1.0f + expf(-e[u][v]));
            Cs[tx * 4 + v][ty * 4 + u] = expf(s);
        }
    __syncthreads();
    float* orow = g_at + ((size_t)b * CCH) * CCH;
    const int jj = tid / 4;
    const int st = (tid % 4) * 16;
    float* dst = &orow[(size_t)(j0 + jj) * CCH + i0 + st];
#pragma unroll
    for (int w = 0; w < 4; w++)
        *(float4*)&dst[w * 4] = *(float4*)&Cs[jj][st + w * 4];
}

// ============================================================================
// K2b: normalize rows of At, round to tf32; ab = row . bias
// ============================================================================
__global__ __launch_bounds__(128) void norm_kernel(const float* __restrict__ vb)
{
    __shared__ float sred[2][4];
    const int b = blockIdx.x >> 9;
    const int j = blockIdx.x & 511;
    float* row = g_at + ((size_t)(b << 9) + j) * CCH;

    const int i4 = threadIdx.x * 4;
    float4 v = *(const float4*)&row[i4];
    float4 w = *(const float4*)&vb[i4];
    float s  = v.x + v.y + v.z + v.w;
    float s2 = v.x * w.x + v.y * w.y + v.z * w.z + v.w * w.w;
#pragma unroll
    for (int o = 16; o > 0; o >>= 1) {
        s  += __shfl_xor_sync(0xffffffffu, s,  o);
        s2 += __shfl_xor_sync(0xffffffffu, s2, o);
    }
    const int wi = threadIdx.x >> 5, li = threadIdx.x & 31;
    if (li == 0) { sred[0][wi] = s; sred[1][wi] = s2; }
    __syncthreads();
    float tot  = sred[0][0] + sred[0][1] + sred[0][2] + sred[0][3];
    float tot2 = sred[1][0] + sred[1][1] + sred[1][2] + sred[1][3];
    float inv = 1.0f / tot;
    v.x = to_tf32(v.x * inv); v.y = to_tf32(v.y * inv);
    v.z = to_tf32(v.z * inv); v.w = to_tf32(v.w * inv);
    *(float4*)&row[i4] = v;
    if (threadIdx.x == 0) g_ab[(b << 9) + j] = tot2 * inv;
}

// ============================================================================
// Transposes (tf32-rounded outputs, MMA B operands)
// ============================================================================
__global__ __launch_bounds__(256) void wt_kernel(const float* __restrict__ W)
{
    __shared__ float t[32][33];
    const int x0 = blockIdx.x * 32, y0 = blockIdx.y * 32;
    const int tx = threadIdx.x, ty = threadIdx.y;
#pragma unroll
    for (int r = 0; r < 32; r += 8) t[ty + r][tx] = W[(y0 + ty + r) * CCH + x0 + tx];
    __syncthreads();
#pragma unroll
    for (int r = 0; r < 32; r += 8)
        g_wt[(x0 + ty + r) * CCH + y0 + tx] = to_tf32(t[tx][ty + r]);
}

__global__ __launch_bounds__(256) void xt_kernel(const float* __restrict__ x)
{
    __shared__ float t[32][33];
    const int b = blockIdx.z;
    const float* in = x + (size_t)b * CCH * NPIX;
    float* out = g_xt + (size_t)b * NPIX * CCH;
    const int n0 = blockIdx.x * 32, c0 = blockIdx.y * 32;
    const int tx = threadIdx.x, ty = threadIdx.y;
#pragma unroll
    for (int r = 0; r < 32; r += 8) t[ty + r][tx] = in[(size_t)(c0 + ty + r) * NPIX + n0 + tx];
    __syncthreads();
#pragma unroll
    for (int r = 0; r < 32; r += 8)
        out[(size_t)(n0 + ty + r) * CCH + c0 + tx] = to_tf32(t[tx][ty + r]);
}

// ============================================================================
// tf32 warp-MMA GEMM: D[m][n] = sum_k A[m][k]*B[n][k], K=512, lda=ldb=512
// Tile 128x128, BK=32, 256 thr (8 warps, 2x4), cp.async double buffer.
// which==0: A=g_at, B=g_wt (shared), C=g_m (tf32-rounded), ldc=512
// which==1: A=g_m,  B=g_xt,          C=outp + bias,        ldc=1024
// ============================================================================
__global__ __launch_bounds__(256, 2) void gemm_mma(int which, float* __restrict__ outp)
{
    extern __shared__ __align__(16) float sm[];
    // layout: A0[0,4K) A1[4K,8K) B0[8K,12K) B1[12K,16K)  (floats)

    const int b = blockIdx.z;
    const int col0 = blockIdx.x * 128, row0 = blockIdx.y * 128;

    const float* A; const float* B; float* C; int ldc;
    if (which == 0) {
        A = g_at + (size_t)b * CCH * CCH;
        B = g_wt;
        C = g_m + (size_t)b * CCH * CCH;
        ldc = CCH;
    } else {
        A = g_m + (size_t)b * CCH * CCH;
        B = g_xt + (size_t)b * NPIX * CCH;
        C = outp + (size_t)b * CCH * NPIX;
        ldc = NPIX;
    }
    const float* Ab = A + (size_t)row0 * CCH;
    const float* Bb = B + (size_t)col0 * CCH;

    const int tid = threadIdx.x;
    const int wid = tid >> 5, lid = tid & 31;
    const int gid = lid >> 2, tig = lid & 3;
    const int wm = wid >> 2, wn = wid & 3;     // 2 x 4 warp grid

    const uint32_t sb = smem_u32(sm);
    // per-thread cp.async source/dest (row = id/8, ch = id%8, xor-swizzle)
    const int ldrow = tid >> 3, ldch = tid & 7;
    const uint32_t sw = (uint32_t)((ldrow * 32 + (((ldch) ^ (ldrow & 7)) << 2)) * 4);

    // issue one K-stage (32 wide) of A and B into buffer `buf`
    auto issue = [&](int s, int buf) {
        const int k0 = s * 32;
        const uint32_t abase = sb + buf * 16384 + sw;
        const uint32_t bbase = sb + 32768 + buf * 16384 + sw;
#pragma unroll
        for (int q = 0; q < 4; q++) {
            int row = ldrow + q * 32;
            cpa16(abase + q * 32 * 128, &Ab[(size_t)row * CCH + k0 + ldch * 4]);
            cpa16(bbase + q * 32 * 128, &Bb[(size_t)row * CCH + k0 + ldch * 4]);
        }
        cpa_commit();
    };

    float acc[4][4][4] = {};
    int mrow[4], ncol[4];
#pragma unroll
    for (int i = 0; i < 4; i++) {
        mrow[i] = wm * 64 + i * 16 + gid;
        ncol[i] = wn * 32 + i * 8 + gid;
    }

    issue(0, 0);

    for (int s = 0; s < 16; s++) {
        const int buf = s & 1;
        if (s < 15) issue(s + 1, buf ^ 1);
        if (s < 15) { asm volatile("cp.async.wait_group 1;" ::: "memory"); }
        else        { asm volatile("cp.async.wait_group 0;" ::: "memory"); }
        __syncthreads();

        const float* as = sm + buf * 4096;
        const float* bs = sm + 8192 + buf * 4096;
#pragma unroll
        for (int kk = 0; kk < 4; kk++) {
            const int c0ch = 2 * kk, c1ch = 2 * kk + 1;
            uint32_t af[4][4], bf[4][2];
#pragma unroll
            for (int mi = 0; mi < 4; mi++) {
                const int r1 = mrow[mi], r2 = r1 + 8;
                af[mi][0] = __float_as_uint(as[r1 * 32 + ((c0ch ^ (r1 & 7)) << 2) + tig]);
                af[mi][1] = __float_as_uint(as[r2 * 32 + ((c0ch ^ (r2 & 7)) << 2) + tig]);
                af[mi][2] = __float_as_uint(as[r1 * 32 + ((c1ch ^ (r1 & 7)) << 2) + tig]);
                af[mi][3] = __float_as_uint(as[r2 * 32 + ((c1ch ^ (r2 & 7)) << 2) + tig]);
            }
#pragma unroll
            for (int ni = 0; ni < 4; ni++) {
                const int cc = ncol[ni];
                bf[ni][0] = __float_as_uint(bs[cc * 32 + ((c0ch ^ (cc & 7)) << 2) + tig]);
                bf[ni][1] = __float_as_uint(bs[cc * 32 + ((c1ch ^ (cc & 7)) << 2) + tig]);
            }
#pragma unroll
            for (int mi = 0; mi < 4; mi++)
#pragma unroll
                for (int ni = 0; ni < 4; ni++)
                    mma_tf32(acc[mi][ni], af[mi], bf[ni]);
        }
        __syncthreads();
    }

    // epilogue
#pragma unroll
    for (int mi = 0; mi < 4; mi++) {
        const int r1 = row0 + wm * 64 + mi * 16 + gid;
        const int r2 = r1 + 8;
        float ab1 = 0.0f, ab2 = 0.0f;
        if (which == 1) { ab1 = g_ab[(b << 9) + r1]; ab2 = g_ab[(b << 9) + r2]; }
#pragma unroll
        for (int ni = 0; ni < 4; ni++) {
            const int cc = col0 + wn * 32 + ni * 8 + tig * 2;
            float* p1 = &C[(size_t)r1 * ldc + cc];
            float* p2 = &C[(size_t)r2 * ldc + cc];
            float c0 = acc[mi][ni][0], c1 = acc[mi][ni][1];
            float c2 = acc[mi][ni][2], c3 = acc[mi][ni][3];
            if (which == 0) {
                c0 = to_tf32(c0); c1 = to_tf32(c1);
                c2 = to_tf32(c2); c3 = to_tf32(c3);
            } else {
                c0 += ab1; c1 += ab1; c2 += ab2; c3 += ab2;
            }
            *(float2*)p1 = make_float2(c0, c1);
            *(float2*)p2 = make_float2(c2, c3);
        }
    }
}

// ============================================================================
extern "C" void kernel_launch(void* const* d_in, const int* in_sizes, int n_in,
                              void* d_out, int out_size)
{
    const float* x  = (const float*)d_in[0];
    const float* qm = (const float*)d_in[1];
    const float* km = (const float*)d_in[2];
    const float* vw = (const float*)d_in[3];
    const float* vb = (const float*)d_in[4];
    float* out = (float*)d_out;

    cudaFuncSetAttribute(gemm_mma, cudaFuncAttributeMaxDynamicSharedMemorySize, 65536);

    qk_kernel    <<<dim3(CCH / 64, BATCH),           256>>>(x, qm, km);
    energy_kernel<<<dim3(CCH / 64, CCH / 64, BATCH), 256>>>();
    norm_kernel  <<<dim3(BATCH * CCH),               128>>>(vb);
    wt_kernel    <<<dim3(16, 16),        dim3(32, 8)>>>(vw);
    xt_kernel    <<<dim3(32, 16, BATCH), dim3(32, 8)>>>(x);
    gemm_mma<<<dim3(CCH / 128,  CCH / 128, BATCH), 256, 65536>>>(0, nullptr);
    gemm_mma<<<dim3(NPIX / 128, CCH / 128, BATCH), 256, 65536>>>(1, out);
}

// round 5
// speedup vs baseline: 2.6262x; 1.2527x over previous
#include <cuda_runtime.h>
#include <cstdint>
#include <math.h>

#define BATCH 64
#define CCH   512
#define NPIX  1024
#define DD    64

// ---------------- scratch (static device arrays) ----------------
__device__ __align__(128) float g_q [BATCH * CCH * DD];
__device__ __align__(128) float g_k [BATCH * CCH * DD];
__device__ __align__(128) float g_at[(size_t)BATCH * CCH * CCH]; // unnormalized T, tf32
__device__ __align__(128) float g_m [(size_t)BATCH * CCH * CCH]; // M, tf32
__device__ __align__(128) float g_ab[BATCH * CCH];               // (T.b)/S per (b,j)
__device__ __align__(128) float g_inv[BATCH * CCH];              // 1/S per (b,j)
__device__ __align__(128) float g_ps [BATCH * CCH * 8];          // partial col sums
__device__ __align__(128) float g_psb[BATCH * CCH * 8];          // partial col bias dots
__device__ __align__(128) float g_wt[CCH * CCH];                 // W^T, tf32
__device__ __align__(128) float g_xt[(size_t)BATCH * NPIX * CCH];// x^T, tf32
__device__ __align__(128) float g_bhi[128 * NPIX];               // [Qm^T;Km^T] hi
__device__ __align__(128) float g_blo[128 * NPIX];               // [Qm^T;Km^T] lo

// ---------------- helpers ----------------
__device__ __forceinline__ float to_tf32(float x) {
    uint32_t u;
    asm("cvt.rna.tf32.f32 %0, %1;" : "=r"(u) : "f"(x));
    return __uint_as_float(u);
}
__device__ __forceinline__ uint32_t smem_u32(const void* p) {
    uint32_t a;
    asm("{ .reg .u64 t; cvta.to.shared.u64 t, %1; cvt.u32.u64 %0, t; }" : "=r"(a) : "l"(p));
    return a;
}
__device__ __forceinline__ void cpa16(uint32_t d, const void* g) {
    asm volatile("cp.async.cg.shared.global [%0], [%1], 16;" :: "r"(d), "l"(g) : "memory");
}
__device__ __forceinline__ void cpa_commit() {
    asm volatile("cp.async.commit_group;" ::: "memory");
}
__device__ __forceinline__ void mma_tf32(float* c, const uint32_t* a, const uint32_t* b) {
    asm volatile(
        "mma.sync.aligned.m16n8k8.row.col.f32.tf32.tf32.f32 "
        "{%0,%1,%2,%3}, {%4,%5,%6,%7}, {%8,%9}, {%0,%1,%2,%3};"
        : "+f"(c[0]), "+f"(c[1]), "+f"(c[2]), "+f"(c[3])
        : "r"(a[0]), "r"(a[1]), "r"(a[2]), "r"(a[3]), "r"(b[0]), "r"(b[1]));
}

// ============================================================================
// prep_b: g_bhi/g_blo[d'][n]: d'<64 -> Qm[n][d'], else Km[n][d'-64], split
// ============================================================================
__global__ __launch_bounds__(256) void prep_b(
    const float* __restrict__ qm, const float* __restrict__ km)
{
    const int n = blockIdx.x * 256 + threadIdx.x;
    const int d = blockIdx.y;
    float v = (d < 64) ? qm[n * 64 + d] : km[n * 64 + (d - 64)];
    float hi = to_tf32(v);
    g_bhi[d * NPIX + n] = hi;
    g_blo[d * NPIX + n] = v - hi;
}

// ============================================================================
// qk3x: [q|k] = x @ [Qm|Km] via 3xTF32 MMA. Tile 128(c) x 128(d'), BK=32.
// grid (4, BATCH), 256 threads, 128KB dynamic smem, double buffered.
// ============================================================================
__global__ __launch_bounds__(256) void qk3x_kernel(const float* __restrict__ x)
{
    extern __shared__ __align__(16) float qs[];
    // per buffer (floats): Ahi[0,4096) Alo[4096,8192) Bhi[8192,12288) Blo[12288,16384)
    const int b = blockIdx.y;
    const int row0 = blockIdx.x * 128;
    const float* A = x + (size_t)b * CCH * NPIX + (size_t)row0 * NPIX;

    const int tid = threadIdx.x;
    const int wid = tid >> 5, lid = tid & 31;
    const int gid = lid >> 2, tig = lid & 3;
    const int wm = wid >> 2, wn = wid & 3;

    const uint32_t sb = smem_u32(qs);
    const int lr = tid >> 3, lc = tid & 7;   // base row, 16B-chunk

    float4 va[4];
    auto ldgA = [&](int s) {
        const int k0 = s * 32;
#pragma unroll
        for (int q = 0; q < 4; q++)
            va[q] = *(const float4*)&A[(size_t)(lr + q * 32) * NPIX + k0 + lc * 4];
    };
    auto stsA = [&](int buf) {
#pragma unroll
        for (int q = 0; q < 4; q++) {
            const int row = lr + q * 32;
            float* hi = qs + buf * 16384 + row * 32 + ((lc ^ (row & 7)) << 2);
            float* lo = hi + 4096;
            float4 h, l;
            h.x = to_tf32(va[q].x); l.x = va[q].x - h.x;
            h.y = to_tf32(va[q].y); l.y = va[q].y - h.y;
            h.z = to_tf32(va[q].z); l.z = va[q].z - h.z;
            h.w = to_tf32(va[q].w); l.w = va[q].w - h.w;
            *(float4*)hi = h;
            *(float4*)lo = l;
        }
    };
    auto cpaB = [&](int s, int buf) {
        const int k0 = s * 32;
#pragma unroll
        for (int q = 0; q < 4; q++) {
            const int row = lr + q * 32;
            const uint32_t off = (uint32_t)((row * 32 + ((lc ^ (row & 7)) << 2)) * 4);
            cpa16(sb + (buf * 16384 + 8192)  * 4 + off, &g_bhi[row * NPIX + k0 + lc * 4]);
            cpa16(sb + (buf * 16384 + 12288) * 4 + off, &g_blo[row * NPIX + k0 + lc * 4]);
        }
        cpa_commit();
    };

    float acc[4][4][4] = {};
    int mrow[4], ncol[4];
#pragma unroll
    for (int i = 0; i < 4; i++) {
        mrow[i] = wm * 64 + i * 16 + gid;
        ncol[i] = wn * 32 + i * 8 + gid;
    }

    ldgA(0);
    cpaB(0, 0);
    stsA(0);

    for (int s = 0; s < 32; s++) {
        const int buf = s & 1;
        asm volatile("cp.async.wait_group 0;" ::: "memory");
        __syncthreads();
        if (s < 31) { ldgA(s + 1); cpaB(s + 1, buf ^ 1); }

        const float* ahs = qs + buf * 16384;
        const float* als = ahs + 4096;
        const float* bhs = ahs + 8192;
        const float* bls = ahs + 12288;
#pragma unroll
        for (int kk = 0; kk < 4; kk++) {
            const int c0 = 2 * kk, c1 = 2 * kk + 1;
            uint32_t ah[4][4], al[4][4], bh[4][2], bl[4][2];
#pragma unroll
            for (int mi = 0; mi < 4; mi++) {
                const int r1 = mrow[mi], r2 = r1 + 8;
                const int o10 = r1 * 32 + ((c0 ^ (r1 & 7)) << 2) + tig;
                const int o20 = r2 * 32 + ((c0 ^ (r2 & 7)) << 2) + tig;
                const int o11 = r1 * 32 + ((c1 ^ (r1 & 7)) << 2) + tig;
                const int o21 = r2 * 32 + ((c1 ^ (r2 & 7)) << 2) + tig;
                ah[mi][0] = __float_as_uint(ahs[o10]); al[mi][0] = __float_as_uint(als[o10]);
                ah[mi][1] = __float_as_uint(ahs[o20]); al[mi][1] = __float_as_uint(als[o20]);
                ah[mi][2] = __float_as_uint(ahs[o11]); al[mi][2] = __float_as_uint(als[o11]);
                ah[mi][3] = __float_as_uint(ahs[o21]); al[mi][3] = __float_as_uint(als[o21]);
            }
#pragma unroll
            for (int ni = 0; ni < 4; ni++) {
                const int cc = ncol[ni];
                const int p0 = cc * 32 + ((c0 ^ (cc & 7)) << 2) + tig;
                const int p1 = cc * 32 + ((c1 ^ (cc & 7)) << 2) + tig;
                bh[ni][0] = __float_as_uint(bhs[p0]); bl[ni][0] = __float_as_uint(bls[p0]);
                bh[ni][1] = __float_as_uint(bhs[p1]); bl[ni][1] = __float_as_uint(bls[p1]);
            }
#pragma unroll
            for (int mi = 0; mi < 4; mi++)
#pragma unroll
                for (int ni = 0; ni < 4; ni++) {
                    mma_tf32(acc[mi][ni], ah[mi], bh[ni]);
                    mma_tf32(acc[mi][ni], ah[mi], bl[ni]);
                    mma_tf32(acc[mi][ni], al[mi], bh[ni]);
                }
        }
        __syncthreads();
        if (s < 31) stsA(buf ^ 1);
    }

    // epilogue: cols <64 -> g_q, >=64 -> g_k
#pragma unroll
    for (int mi = 0; mi < 4; mi++) {
        const int r1 = row0 + wm * 64 + mi * 16 + gid;
        const int r2 = r1 + 8;
#pragma unroll
        for (int ni = 0; ni < 4; ni++) {
            const int d = wn * 32 + ni * 8 + tig * 2;
            float* base = (d < 64) ? g_q : g_k;
            const int dc = d & 63;
            float* p1 = base + ((size_t)b * CCH + r1) * DD + dc;
            float* p2 = base + ((size_t)b * CCH + r2) * DD + dc;
            *(float2*)p1 = make_float2(acc[mi][ni][0], acc[mi][ni][1]);
            *(float2*)p2 = make_float2(acc[mi][ni][2], acc[mi][ni][3]);
        }
    }
}

// ============================================================================
// energy: At[b][j][i] = tf32(exp(sigmoid(e))) unnormalized; partial col sums.
// fp32 GEMM (accuracy-critical), saturation fast path for MUFU.
// ============================================================================
__global__ __launch_bounds__(256) void energy_kernel(const float* __restrict__ vb)
{
    __shared__ float Qs[16][64];
    __shared__ float Ks[16][64];
    __shared__ float Cs[64][68];

    const int b  = blockIdx.z;
    const int j0 = blockIdx.x * 64;
    const int i0 = blockIdx.y * 64;
    const float* Aq = g_q + ((size_t)b * CCH + i0) * DD;
    const float* Ak = g_k + ((size_t)b * CCH + j0) * DD;

    const int tid = threadIdx.x;
    const int ty = tid / 16, tx = tid % 16;
    const int ar = tid / 4,  ac = (tid % 4) * 4;

    float e[4][4] = {};
    for (int k0 = 0; k0 < DD; k0 += 16) {
        float4 av = *(const float4*)&Aq[ar * DD + k0 + ac];
        Qs[ac + 0][ar] = av.x; Qs[ac + 1][ar] = av.y;
        Qs[ac + 2][ar] = av.z; Qs[ac + 3][ar] = av.w;
        float4 bv = *(const float4*)&Ak[ar * DD + k0 + ac];
        Ks[ac + 0][ar] = bv.x; Ks[ac + 1][ar] = bv.y;
        Ks[ac + 2][ar] = bv.z; Ks[ac + 3][ar] = bv.w;
        __syncthreads();
#pragma unroll
        for (int kk = 0; kk < 16; kk++) {
            float a[4], bb[4];
#pragma unroll
            for (int u = 0; u < 4; u++) a[u]  = Qs[kk][ty * 4 + u];
#pragma unroll
            for (int v = 0; v < 4; v++) bb[v] = Ks[kk][tx * 4 + v];
#pragma unroll
            for (int u = 0; u < 4; u++)
#pragma unroll
                for (int v = 0; v < 4; v++) e[u][v] = fmaf(a[u], bb[v], e[u][v]);
        }
        __syncthreads();
    }

    // T = exp(sigmoid(e)); 99.9% saturate (|e|>12 -> sigmoid = 0/1 to 6e-6)
    float t[4][4];
    bool need = false;
#pragma unroll
    for (int u = 0; u < 4; u++)
#pragma unroll
        for (int v = 0; v < 4; v++) need |= (fabsf(e[u][v]) < 12.0f);
    if (__any_sync(0xffffffffu, need)) {
#pragma unroll
        for (int u = 0; u < 4; u++)
#pragma unroll
            for (int v = 0; v < 4; v++) {
                float s = 1.0f / (1.0f + __expf(-e[u][v]));
                t[u][v] = __expf(s);
            }
    } else {
#pragma unroll
        for (int u = 0; u < 4; u++)
#pragma unroll
            for (int v = 0; v < 4; v++)
                t[u][v] = (e[u][v] > 0.0f) ? 2.71828182845904523536f : 1.0f;
    }
#pragma unroll
    for (int u = 0; u < 4; u++)
#pragma unroll
        for (int v = 0; v < 4; v++)
            Cs[tx * 4 + v][ty * 4 + u] = to_tf32(t[u][v]);
    __syncthreads();

    // coalesced transposed write + per-j partial sums over this i-tile
    float* orow = g_at + ((size_t)b * CCH) * CCH;
    const int jj = tid / 4;
    const int st = (tid % 4) * 16;
    float* dst = &orow[(size_t)(j0 + jj) * CCH + i0 + st];
    float s = 0.0f, sbias = 0.0f;
#pragma unroll
    for (int w = 0; w < 4; w++) {
        float4 v4 = *(float4*)&Cs[jj][st + w * 4];
        const float* bb = &vb[i0 + st + w * 4];
        s += v4.x + v4.y + v4.z + v4.w;
        sbias += v4.x * bb[0] + v4.y * bb[1] + v4.z * bb[2] + v4.w * bb[3];
        *(float4*)&dst[w * 4] = v4;
    }
    s += __shfl_xor_sync(0xffffffffu, s, 1);
    s += __shfl_xor_sync(0xffffffffu, s, 2);
    sbias += __shfl_xor_sync(0xffffffffu, sbias, 1);
    sbias += __shfl_xor_sync(0xffffffffu, sbias, 2);
    if ((tid & 3) == 0) {
        const int idx = ((b << 9) + j0 + jj) * 8 + blockIdx.y;
        g_ps[idx]  = s;
        g_psb[idx] = sbias;
    }
}

// ============================================================================
// reduce: S, TB -> g_inv = 1/S, g_ab = TB/S
// ============================================================================
__global__ __launch_bounds__(256) void reduce_kernel()
{
    const int idx = blockIdx.x * 256 + threadIdx.x;   // over 64*512
    float S = 0.0f, TB = 0.0f;
#pragma unroll
    for (int r = 0; r < 8; r++) { S += g_ps[idx * 8 + r]; TB += g_psb[idx * 8 + r]; }
    g_inv[idx] = 1.0f / S;
    g_ab[idx]  = TB / S;
}

// ============================================================================
// Transposes
// ============================================================================
__global__ __launch_bounds__(256) void wt_kernel(const float* __restrict__ W)
{
    __shared__ float t[32][33];
    const int x0 = blockIdx.x * 32, y0 = blockIdx.y * 32;
    const int tx = threadIdx.x, ty = threadIdx.y;
#pragma unroll
    for (int r = 0; r < 32; r += 8) t[ty + r][tx] = W[(y0 + ty + r) * CCH + x0 + tx];
    __syncthreads();
#pragma unroll
    for (int r = 0; r < 32; r += 8)
        g_wt[(x0 + ty + r) * CCH + y0 + tx] = to_tf32(t[tx][ty + r]);
}

__global__ __launch_bounds__(256) void xt_kernel(const float* __restrict__ x)
{
    __shared__ float t[32][33];
    const int b = blockIdx.z;
    const float* in = x + (size_t)b * CCH * NPIX;
    float* out = g_xt + (size_t)b * NPIX * CCH;
    const int n0 = blockIdx.x * 32, c0 = blockIdx.y * 32;
    const int tx = threadIdx.x, ty = threadIdx.y;
#pragma unroll
    for (int r = 0; r < 32; r += 8) t[ty + r][tx] = in[(size_t)(c0 + ty + r) * NPIX + n0 + tx];
    __syncthreads();
#pragma unroll
    for (int r = 0; r < 32; r += 8)
        out[(size_t)(n0 + ty + r) * CCH + c0 + tx] = to_tf32(t[tx][ty + r]);
}

// ============================================================================
// tf32 warp-MMA GEMM 128x128, BK=32, cp.async double buffer.
// which==0: M = (At @ Wt) scaled by 1/S_j, tf32-rounded -> g_m
// which==1: out = M @ xT + ab
// ============================================================================
__global__ __launch_bounds__(256, 2) void gemm_mma(int which, float* __restrict__ outp)
{
    extern __shared__ __align__(16) float sm[];

    const int b = blockIdx.z;
    const int col0 = blockIdx.x * 128, row0 = blockIdx.y * 128;

    const float* A; const float* B; float* C; int ldc;
    if (which == 0) {
        A = g_at + (size_t)b * CCH * CCH;
        B = g_wt;
        C = g_m + (size_t)b * CCH * CCH;
        ldc = CCH;
    } else {
        A = g_m + (size_t)b * CCH * CCH;
        B = g_xt + (size_t)b * NPIX * CCH;
        C = outp + (size_t)b * CCH * NPIX;
        ldc = NPIX;
    }
    const float* Ab = A + (size_t)row0 * CCH;
    const float* Bb = B + (size_t)col0 * CCH;

    const int tid = threadIdx.x;
    const int wid = tid >> 5, lid = tid & 31;
    const int gid = lid >> 2, tig = lid & 3;
    const int wm = wid >> 2, wn = wid & 3;

    const uint32_t sb = smem_u32(sm);
    const int ldrow = tid >> 3, ldch = tid & 7;
    const uint32_t sw = (uint32_t)((ldrow * 32 + (((ldch) ^ (ldrow & 7)) << 2)) * 4);

    auto issue = [&](int s, int buf) {
        const int k0 = s * 32;
        const uint32_t abase = sb + buf * 16384 + sw;
        const uint32_t bbase = sb + 32768 + buf * 16384 + sw;
#pragma unroll
        for (int q = 0; q < 4; q++) {
            int row = ldrow + q * 32;
            cpa16(abase + q * 32 * 128, &Ab[(size_t)row * CCH + k0 + ldch * 4]);
            cpa16(bbase + q * 32 * 128, &Bb[(size_t)row * CCH + k0 + ldch * 4]);
        }
        cpa_commit();
    };

    float acc[4][4][4] = {};
    int mrow[4], ncol[4];
#pragma unroll
    for (int i = 0; i < 4; i++) {
        mrow[i] = wm * 64 + i * 16 + gid;
        ncol[i] = wn * 32 + i * 8 + gid;
    }

    issue(0, 0);

    for (int s = 0; s < 16; s++) {
        const int buf = s & 1;
        if (s < 15) issue(s + 1, buf ^ 1);
        if (s < 15) { asm volatile("cp.async.wait_group 1;" ::: "memory"); }
        else        { asm volatile("cp.async.wait_group 0;" ::: "memory"); }
        __syncthreads();

        const float* as = sm + buf * 4096;
        const float* bs = sm + 8192 + buf * 4096;
#pragma unroll
        for (int kk = 0; kk < 4; kk++) {
            const int c0ch = 2 * kk, c1ch = 2 * kk + 1;
            uint32_t af[4][4], bf[4][2];
#pragma unroll
            for (int mi = 0; mi < 4; mi++) {
                const int r1 = mrow[mi], r2 = r1 + 8;
                af[mi][0] = __float_as_uint(as[r1 * 32 + ((c0ch ^ (r1 & 7)) << 2) + tig]);
                af[mi][1] = __float_as_uint(as[r2 * 32 + ((c0ch ^ (r2 & 7)) << 2) + tig]);
                af[mi][2] = __float_as_uint(as[r1 * 32 + ((c1ch ^ (r1 & 7)) << 2) + tig]);
                af[mi][3] = __float_as_uint(as[r2 * 32 + ((c1ch ^ (r2 & 7)) << 2) + tig]);
            }
#pragma unroll
            for (int ni = 0; ni < 4; ni++) {
                const int cc = ncol[ni];
                bf[ni][0] = __float_as_uint(bs[cc * 32 + ((c0ch ^ (cc & 7)) << 2) + tig]);
                bf[ni][1] = __float_as_uint(bs[cc * 32 + ((c1ch ^ (cc & 7)) << 2) + tig]);
            }
#pragma unroll
            for (int mi = 0; mi < 4; mi++)
#pragma unroll
                for (int ni = 0; ni < 4; ni++)
                    mma_tf32(acc[mi][ni], af[mi], bf[ni]);
        }
        __syncthreads();
    }

    // epilogue
#pragma unroll
    for (int mi = 0; mi < 4; mi++) {
        const int r1 = row0 + wm * 64 + mi * 16 + gid;
        const int r2 = r1 + 8;
        float s1, s2;
        if (which == 0) { s1 = g_inv[(b << 9) + r1]; s2 = g_inv[(b << 9) + r2]; }
        else            { s1 = g_ab [(b << 9) + r1]; s2 = g_ab [(b << 9) + r2]; }
#pragma unroll
        for (int ni = 0; ni < 4; ni++) {
            const int cc = col0 + wn * 32 + ni * 8 + tig * 2;
            float* p1 = &C[(size_t)r1 * ldc + cc];
            float* p2 = &C[(size_t)r2 * ldc + cc];
            float c0 = acc[mi][ni][0], c1 = acc[mi][ni][1];
            float c2 = acc[mi][ni][2], c3 = acc[mi][ni][3];
            if (which == 0) {
                c0 = to_tf32(c0 * s1); c1 = to_tf32(c1 * s1);
                c2 = to_tf32(c2 * s2); c3 = to_tf32(c3 * s2);
            } else {
                c0 += s1; c1 += s1; c2 += s2; c3 += s2;
            }
            *(float2*)p1 = make_float2(c0, c1);
            *(float2*)p2 = make_float2(c2, c3);
        }
    }
}

// ============================================================================
extern "C" void kernel_launch(void* const* d_in, const int* in_sizes, int n_in,
                              void* d_out, int out_size)
{
    const float* x  = (const float*)d_in[0];
    const float* qm = (const float*)d_in[1];
    const float* km = (const float*)d_in[2];
    const float* vw = (const float*)d_in[3];
    const float* vb = (const float*)d_in[4];
    float* out = (float*)d_out;

    cudaFuncSetAttribute(gemm_mma,    cudaFuncAttributeMaxDynamicSharedMemorySize, 65536);
    cudaFuncSetAttribute(qk3x_kernel, cudaFuncAttributeMaxDynamicSharedMemorySize, 131072);

    prep_b       <<<dim3(NPIX / 256, 128),           256>>>(qm, km);
    qk3x_kernel  <<<dim3(4, BATCH),                  256, 131072>>>(x);
    energy_kernel<<<dim3(CCH / 64, CCH / 64, BATCH), 256>>>(vb);
    reduce_kernel<<<dim3(BATCH * CCH / 256),         256>>>();
    wt_kernel    <<<dim3(16, 16),        dim3(32, 8)>>>(vw);
    xt_kernel    <<<dim3(32, 16, BATCH), dim3(32, 8)>>>(x);
    gemm_mma<<<dim3(CCH / 128,  CCH / 128, BATCH), 256, 65536>>>(0, nullptr);
    gemm_mma<<<dim3(NPIX / 128, CCH / 128, BATCH), 256, 65536>>>(1, out);
}